// round 11
// baseline (speedup 1.0000x reference)
#include <cuda_runtime.h>
#include <cuda_bf16.h>
#include <cuda_fp16.h>
#include <math.h>
#include <cstdint>

#define BB   2
#define TT   4096
#define DD   768
#define HH   12
#define HDIM 64
#define QKV3 (3*DD)       // 2304
#define ATT_SCALE 0.125f  // 1/sqrt(64)

#if !defined(__CUDA_ARCH__)
#define HAS_TC 1
#elif defined(__CUDA_ARCH_FEAT_SM103_ALL)
#define HAS_TC 1
#elif defined(__CUDA_ARCH_SPECIFIC__) && (__CUDA_ARCH_SPECIFIC__ == 1030)
#define HAS_TC 1
#elif defined(__CUDA_ARCH_FAMILY_SPECIFIC__) && (__CUDA_ARCH_FAMILY_SPECIFIC__ >= 1000)
#define HAS_TC 1
#else
#define HAS_TC 0
#endif

// ---------------- scratch ----------------
__device__ __nv_bfloat16 g_xhi [(size_t)BB*TT*DD];
__device__ __nv_bfloat16 g_xlo [(size_t)BB*TT*DD];
__device__ __nv_bfloat16 g_ahi [(size_t)BB*TT*DD];
__device__ __nv_bfloat16 g_alo [(size_t)BB*TT*DD];
__device__ __nv_bfloat16 g_wqt_hi[(size_t)QKV3*DD];
__device__ __nv_bfloat16 g_wqt_lo[(size_t)QKV3*DD];
__device__ __nv_bfloat16 g_wot_hi[(size_t)DD*DD];
__device__ __nv_bfloat16 g_wot_lo[(size_t)DD*DD];
__device__ __nv_bfloat16 g_qh [(size_t)BB*HH*TT*HDIM];   // [bh][t][d]
__device__ __nv_bfloat16 g_ql [(size_t)BB*HH*TT*HDIM];
__device__ __nv_bfloat16 g_kh [(size_t)BB*HH*TT*HDIM];
__device__ __nv_bfloat16 g_kl [(size_t)BB*HH*TT*HDIM];
__device__ __half        g_vt [(size_t)BB*HH*HDIM*TT];   // [bh][d][t]

// ---------------- helpers ----------------
__device__ __forceinline__ uint32_t smem_u32(const void* p) {
    uint32_t a;
    asm("{ .reg .u64 t; cvta.to.shared.u64 t, %1; cvt.u32.u64 %0, t; }"
        : "=r"(a) : "l"(p));
    return a;
}
#define SMEM_SWIZZLE_128B(off) ((off) ^ (((off) >> 3) & 0x70))

#if HAS_TC
__device__ __forceinline__ uint32_t elect_one() {
    uint32_t pred;
    asm volatile("{\n\t.reg .pred p;\n\telect.sync _|p, 0xFFFFFFFF;\n\t"
                 "selp.b32 %0, 1, 0, p;\n\t}" : "=r"(pred));
    return pred;
}
static constexpr uint64_t SMEM_DESC_BASE_SW128 =
    (uint64_t(2) << 61) | (uint64_t(1) << 46) | (uint64_t(64) << 32) | (uint64_t(1) << 16);
#define MAKE_SMEM_DESC(addr) (SMEM_DESC_BASE_SW128 | ((uint64_t)((addr) >> 4) & 0x3FFF))

#define TCGEN05_ALLOC(sa, n) \
    asm volatile("tcgen05.alloc.cta_group::1.sync.aligned.shared::cta.b32 [%0], %1;" \
                 :: "r"((uint32_t)(sa)), "r"((uint32_t)(n)) : "memory")
#define TCGEN05_DEALLOC(t, n) \
    asm volatile("tcgen05.dealloc.cta_group::1.sync.aligned.b32 %0, %1;" :: "r"(t), "r"(n))
#define TCGEN05_RELINQ() \
    asm volatile("tcgen05.relinquish_alloc_permit.cta_group::1.sync.aligned;")
#define TCGEN05_COMMIT(mb) \
    asm volatile("tcgen05.commit.cta_group::1.mbarrier::arrive::one.shared::cluster.b64 [%0];" \
                 :: "r"((uint32_t)(mb)) : "memory")
#define TCGEN05_FENCE_AFTER() \
    asm volatile("tcgen05.fence::after_thread_sync;" ::: "memory")
#define TCGEN05_FENCE_BEFORE() \
    asm volatile("tcgen05.fence::before_thread_sync;" ::: "memory")
#define TCGEN05_WAIT_LD() \
    asm volatile("tcgen05.wait::ld.sync.aligned;" ::: "memory")
#define FENCE_PROXY_ASYNC() \
    asm volatile("fence.proxy.async.shared::cta;" ::: "memory")
#define MBARRIER_INIT(mb, cnt) \
    asm volatile("mbarrier.init.shared.b64 [%0], %1;" \
                 :: "r"((uint32_t)(mb)), "r"((uint32_t)(cnt)) : "memory")
#define MBARRIER_WAIT_PARITY(mb, ph) do {                                   \
    uint32_t _m = (uint32_t)(mb); uint32_t _p = (uint32_t)(ph);             \
    asm volatile("{\n\t.reg .pred P1;\n\t"                                  \
        "WL_%=:\n\t"                                                        \
        "mbarrier.try_wait.parity.acquire.cta.shared::cta.b64 P1, [%0], %1, 0x989680;\n\t" \
        "@P1 bra.uni WD_%=;\n\t"                                            \
        "bra.uni WL_%=;\n\t"                                                \
        "WD_%=:\n\t}" :: "r"(_m), "r"(_p) : "memory");                      \
} while (0)
#define CP_ASYNC16(dst, src) \
    asm volatile("cp.async.cg.shared.global [%0], [%1], 16;" \
                 :: "r"((uint32_t)(dst)), "l"(src) : "memory")
#define CP_COMMIT() asm volatile("cp.async.commit_group;" ::: "memory")
#define CP_WAIT0()  asm volatile("cp.async.wait_group 0;" ::: "memory")
// .noinc: arrive WITHOUT pre-incrementing expected count (barrier init'd with
// thread count). The default form pre-increments and was the round-10 deadlock.
#define CP_MBAR_ARRIVE_NOINC(mb) \
    asm volatile("cp.async.mbarrier.arrive.noinc.shared::cta.b64 [%0];" \
                 :: "r"((uint32_t)(mb)) : "memory")
#define BAR_SYNC(id, n)   asm volatile("bar.sync %0, %1;"   :: "r"(id), "r"(n) : "memory")
#define BAR_ARRIVE(id, n) asm volatile("bar.arrive %0, %1;" :: "r"(id), "r"(n) : "memory")

__device__ __forceinline__ void mma_f16_ss_cg1(
    uint32_t d_tmem, uint64_t a_desc, uint64_t b_desc, uint32_t idesc, uint32_t en)
{
    asm volatile(
        "{\n\t.reg .pred p;\n\tsetp.ne.u32 p, %5, 0;\n\t"
        "tcgen05.mma.cta_group::1.kind::f16 [%0], %1, %2, %3, {%4, %4, %4, %4}, p;\n\t}"
        :: "r"(d_tmem), "l"(a_desc), "l"(b_desc), "r"(idesc), "r"(0u), "r"(en)
        : "memory");
}
#define LDTM_X32(r, addr)                                                    \
    asm volatile("tcgen05.ld.sync.aligned.32x32b.x32.b32 "                   \
        "{%0, %1, %2, %3, %4, %5, %6, %7, %8, %9, %10, %11, %12, %13, %14, %15, " \
        " %16, %17, %18, %19, %20, %21, %22, %23, %24, %25, %26, %27, %28, %29, %30, %31}, [%32];" \
        : "=r"((r)[0]),  "=r"((r)[1]),  "=r"((r)[2]),  "=r"((r)[3]),         \
          "=r"((r)[4]),  "=r"((r)[5]),  "=r"((r)[6]),  "=r"((r)[7]),         \
          "=r"((r)[8]),  "=r"((r)[9]),  "=r"((r)[10]), "=r"((r)[11]),        \
          "=r"((r)[12]), "=r"((r)[13]), "=r"((r)[14]), "=r"((r)[15]),        \
          "=r"((r)[16]), "=r"((r)[17]), "=r"((r)[18]), "=r"((r)[19]),        \
          "=r"((r)[20]), "=r"((r)[21]), "=r"((r)[22]), "=r"((r)[23]),        \
          "=r"((r)[24]), "=r"((r)[25]), "=r"((r)[26]), "=r"((r)[27]),        \
          "=r"((r)[28]), "=r"((r)[29]), "=r"((r)[30]), "=r"((r)[31])         \
        : "r"(addr))
#endif  // HAS_TC

// ---------------- prep kernels ----------------
__global__ __launch_bounds__(256) void split_hl(
    const float* __restrict__ src, __nv_bfloat16* __restrict__ hi,
    __nv_bfloat16* __restrict__ lo, int n4)
{
    int i = blockIdx.x * 256 + threadIdx.x;
    if (i >= n4) return;
    float4 v = ((const float4*)src)[i];
    float vs[4] = {v.x, v.y, v.z, v.w};
    __nv_bfloat16 h[4], l[4];
#pragma unroll
    for (int j = 0; j < 4; j++) {
        h[j] = __float2bfloat16(vs[j]);
        l[j] = __float2bfloat16(vs[j] - __bfloat162float(h[j]));
    }
    ((__nv_bfloat162*)hi)[2*i]   = __halves2bfloat162(h[0], h[1]);
    ((__nv_bfloat162*)hi)[2*i+1] = __halves2bfloat162(h[2], h[3]);
    ((__nv_bfloat162*)lo)[2*i]   = __halves2bfloat162(l[0], l[1]);
    ((__nv_bfloat162*)lo)[2*i+1] = __halves2bfloat162(l[2], l[3]);
}

__global__ void tsplit_kernel(
    const float* __restrict__ W, __nv_bfloat16* __restrict__ Thi,
    __nv_bfloat16* __restrict__ Tlo, int K, int N)
{
    __shared__ float t[32][33];
    int kb = blockIdx.x * 32, nb = blockIdx.y * 32;
    int tx = threadIdx.x, ty = threadIdx.y;
#pragma unroll
    for (int i = 0; i < 4; i++) {
        int k = ty + i * 8;
        t[k][tx] = W[(size_t)(kb + k) * N + nb + tx];
    }
    __syncthreads();
#pragma unroll
    for (int i = 0; i < 4; i++) {
        int nr = ty + i * 8;
        float v = t[tx][nr];
        __nv_bfloat16 h = __float2bfloat16(v);
        __nv_bfloat16 l = __float2bfloat16(v - __bfloat162float(h));
        size_t o = (size_t)(nb + nr) * K + kb + tx;
        Thi[o] = h; Tlo[o] = l;
    }
}

// ---------------- tcgen05 GEMM (round-9 verified): 128x256, 2 CTA/SM -------
#define GB_AH 0
#define GB_AL 16384
#define GB_BH 32768
#define GB_BL 65536
#define GB_SZ 98304
#define GSM_BUF 1024
#define GEMM_SMEM (GSM_BUF + GB_SZ)      // 99328 -> 2 CTAs/SM
#define GEMM_IDESC 0x8400490u            // f32 acc, bf16xbf16, M=128, N=256

#if HAS_TC
__device__ __forceinline__ void gemm_prefetch(
    uint32_t sbuf, const char* Ah, const char* Al, const char* Bh, const char* Bl,
    int K, int m0, int n0, int k0, int tid)
{
#pragma unroll
    for (int p = 0; p < 4; p++) {           // A: 128 rows x 128B x 2 planes
        int i = tid + p * 256;
        int r = i >> 3, c16 = (i & 7) << 4;
        uint32_t so = SMEM_SWIZZLE_128B(r * 128 + c16);
        size_t go = ((size_t)(m0 + r) * K + k0) * 2 + c16;
        CP_ASYNC16(sbuf + GB_AH + so, Ah + go);
        CP_ASYNC16(sbuf + GB_AL + so, Al + go);
    }
#pragma unroll
    for (int p = 0; p < 8; p++) {           // B: 256 rows x 128B x 2 planes
        int i = tid + p * 256;
        int r = i >> 3, c16 = (i & 7) << 4;
        uint32_t so = SMEM_SWIZZLE_128B(r * 128 + c16);
        size_t go = ((size_t)(n0 + r) * K + k0) * 2 + c16;
        CP_ASYNC16(sbuf + GB_BH + so, Bh + go);
        CP_ASYNC16(sbuf + GB_BL + so, Bl + go);
    }
}
#endif

__global__ __launch_bounds__(256) void gemm_any(
    const __nv_bfloat16* __restrict__ Ahi, const __nv_bfloat16* __restrict__ Alo,
    const __nv_bfloat16* __restrict__ Bthi, const __nv_bfloat16* __restrict__ Btlo,
    const float* __restrict__ bias, float* __restrict__ C,
    int M, int N, int K, int mode)
{
    extern __shared__ char smem[];
#if HAS_TC
    const uint32_t sb = smem_u32(smem);
    const int tid = threadIdx.x;
    const int wid = tid >> 5, lid = tid & 31;
    const int m0 = blockIdx.y * 128, n0 = blockIdx.x * 256;
    const char* Ah = (const char*)Ahi;  const char* Al = (const char*)Alo;
    const char* Bh = (const char*)Bthi; const char* Bl = (const char*)Btlo;

    if (wid == 0) { TCGEN05_ALLOC(sb, 256); TCGEN05_RELINQ(); }
    if (tid == 0) MBARRIER_INIT(sb + 8, 1);
    __syncthreads();
    uint32_t tmem;
    asm volatile("ld.shared.b32 %0, [%1];" : "=r"(tmem) : "r"(sb));

    const uint64_t dAh = MAKE_SMEM_DESC(sb + GSM_BUF + GB_AH);
    const uint64_t dAl = MAKE_SMEM_DESC(sb + GSM_BUF + GB_AL);
    const uint64_t dBh = MAKE_SMEM_DESC(sb + GSM_BUF + GB_BH);
    const uint64_t dBl = MAKE_SMEM_DESC(sb + GSM_BUF + GB_BL);

    const int nchunks = K >> 6;   // 12
    for (int c = 0; c < nchunks; c++) {
        gemm_prefetch(sb + GSM_BUF, Ah, Al, Bh, Bl, K, m0, n0, c * 64, tid);
        CP_COMMIT();
        CP_WAIT0();
        __syncthreads();

        if (wid == 0 && elect_one()) {
#pragma unroll
            for (int ks = 0; ks < 4; ks++) {
                uint32_t en0 = (c > 0 || ks > 0) ? 1u : 0u;
                mma_f16_ss_cg1(tmem, dAh + ks*2, dBh + ks*2, GEMM_IDESC, en0);
                mma_f16_ss_cg1(tmem, dAh + ks*2, dBl + ks*2, GEMM_IDESC, 1u);
                mma_f16_ss_cg1(tmem, dAl + ks*2, dBh + ks*2, GEMM_IDESC, 1u);
            }
            TCGEN05_COMMIT(sb + 8);
        }
        MBARRIER_WAIT_PARITY(sb + 8, c & 1);
    }

    TCGEN05_FENCE_AFTER();
    {   // 8-warp epilogue: warps split 256 cols into 2 halves
        const int row = m0 + (wid & 3) * 32 + lid;
        const int cbase = (wid >> 2) * 128;
        const int b  = row >> 12;
        const int t  = row & 4095;
#pragma unroll
        for (int base = 0; base < 128; base += 32) {
            uint32_t rg[32];
            LDTM_X32(rg, tmem + cbase + base);
            TCGEN05_WAIT_LD();
            const int col0 = n0 + cbase + base;
            const float* bp = bias + col0;
            if (mode == 0) {
                float* crow = C + (size_t)row * N + col0;
#pragma unroll
                for (int j = 0; j < 32; j += 4) {
                    float4 o = make_float4(__uint_as_float(rg[j])   + bp[j],
                                           __uint_as_float(rg[j+1]) + bp[j+1],
                                           __uint_as_float(rg[j+2]) + bp[j+2],
                                           __uint_as_float(rg[j+3]) + bp[j+3]);
                    *(float4*)(crow + j) = o;
                }
            } else {
                const int sec  = col0 / DD;          // 0=q 1=k 2=v
                const int rcol = col0 - sec * DD;
                const int h    = rcol >> 6;
                const int d0   = rcol & 63;          // 0 or 32
                const int bh   = b * HH + h;
                if (sec < 2) {
                    __nv_bfloat16* dh = (sec ? g_kh : g_qh);
                    __nv_bfloat16* dl = (sec ? g_kl : g_ql);
                    size_t off = (((size_t)bh * TT + t) << 6) + d0;
                    uint32_t hp[16], lp[16];
#pragma unroll
                    for (int j2 = 0; j2 < 16; j2++) {
                        float v0 = __uint_as_float(rg[2*j2])   + bp[2*j2];
                        float v1 = __uint_as_float(rg[2*j2+1]) + bp[2*j2+1];
                        __nv_bfloat16 h0 = __float2bfloat16(v0), h1 = __float2bfloat16(v1);
                        __nv_bfloat16 l0 = __float2bfloat16(v0 - __bfloat162float(h0));
                        __nv_bfloat16 l1 = __float2bfloat16(v1 - __bfloat162float(h1));
                        __nv_bfloat162 hh = __halves2bfloat162(h0, h1);
                        __nv_bfloat162 ll = __halves2bfloat162(l0, l1);
                        hp[j2] = *(uint32_t*)&hh; lp[j2] = *(uint32_t*)&ll;
                    }
#pragma unroll
                    for (int k4 = 0; k4 < 4; k4++) {
                        *(uint4*)((char*)dh + off*2 + k4*16) = ((uint4*)hp)[k4];
                        *(uint4*)((char*)dl + off*2 + k4*16) = ((uint4*)lp)[k4];
                    }
                } else {
                    __half* dst = g_vt + (((size_t)bh << 6) + d0) * TT + t;
#pragma unroll
                    for (int j = 0; j < 32; j++)
                        dst[(size_t)j * TT] = __float2half(__uint_as_float(rg[j]) + bp[j]);
                }
            }
        }
    }
    __syncthreads();
    if (wid == 0) TCGEN05_DEALLOC(tmem, 256);
#else
    const int tid = threadIdx.x;
    for (int idx = (blockIdx.y * gridDim.x + blockIdx.x) * 256 + tid;
         idx < M * N; idx += gridDim.x * gridDim.y * 256) {
        int row = idx / N, col = idx % N;
        float acc = bias[col];
        for (int k = 0; k < K; k++)
            acc += __bfloat162float(Ahi[(size_t)row*K+k]) * __bfloat162float(Bthi[(size_t)col*K+k])
                 + __bfloat162float(Alo[(size_t)row*K+k]) * __bfloat162float(Bthi[(size_t)col*K+k])
                 + __bfloat162float(Ahi[(size_t)row*K+k]) * __bfloat162float(Btlo[(size_t)col*K+k]);
        if (mode == 0) {
            C[idx] = acc;
        } else {
            int b = row >> 12, t = row & 4095;
            int sec = col / DD, rcol = col - sec * DD;
            int h = rcol >> 6, d = rcol & 63, bh = b * HH + h;
            if (sec < 2) {
                __nv_bfloat16 hv = __float2bfloat16(acc);
                __nv_bfloat16 lv = __float2bfloat16(acc - __bfloat162float(hv));
                size_t off = (((size_t)bh * TT + t) << 6) + d;
                (sec ? g_kh : g_qh)[off] = hv;
                (sec ? g_kl : g_ql)[off] = lv;
            } else {
                g_vt[(((size_t)bh << 6) + d) * TT + t] = __float2half(acc);
            }
        }
    }
#endif
}

// ---------------- tcgen05 flash attention (512 thr, no per-iter syncthreads)
#define ASM_TPTR 0
#define ASM_MBS0 8
#define ASM_MBS1 16
#define ASM_MBPV 24
#define ASM_MBK0 32
#define ASM_MBK1 40
#define ASM_QH   1024
#define ASM_QL   (ASM_QH + 16384)
#define ASM_K0H  (ASM_QL + 16384)
#define ASM_K0L  (ASM_K0H + 16384)
#define ASM_K1H  (ASM_K0L + 16384)
#define ASM_K1L  (ASM_K1H + 16384)
#define ASM_V    (ASM_K1L + 16384)         // 3 x 16KB
#define ASM_P    (ASM_V + 49152)           // 32KB
#define ASM_LP   (ASM_P + 32768)           // 4 x 128 floats
#define ATT_SMEM (ASM_LP + 2048)           // 183296
#define IDESC_S      0x8200490u            // M=128 N=128 bf16->f32
#define IDESC_PV_F16 0x8100010u            // M=128 N=64  f16->f32
// TMEM: S0 @0, S1 @128, O @256

__global__ __launch_bounds__(512) void attn_tc()
{
#if HAS_TC
    extern __shared__ char smem[];
    const uint32_t sb = smem_u32(smem);
    const int tid = threadIdx.x;
    const int w = tid >> 5, lid = tid & 31;
    const int bh = blockIdx.y;
    const int qt = gridDim.x - 1 - blockIdx.x;
    const int q0 = qt * 128;
    const int r  = (w & 3) * 32 + lid;     // owned row
    const int cq = w >> 2;                 // col quarter 0..3

    const char* qh = (const char*)(g_qh + (size_t)bh*TT*HDIM);
    const char* ql = (const char*)(g_ql + (size_t)bh*TT*HDIM);
    const char* kh = (const char*)(g_kh + (size_t)bh*TT*HDIM);
    const char* kl = (const char*)(g_kl + (size_t)bh*TT*HDIM);
    const char* vt = (const char*)(g_vt + (size_t)bh*HDIM*TT);

    if (w == 0) { TCGEN05_ALLOC(sb + ASM_TPTR, 512); TCGEN05_RELINQ(); }
    if (tid == 0) {
        MBARRIER_INIT(sb + ASM_MBS0, 1);
        MBARRIER_INIT(sb + ASM_MBS1, 1);
        MBARRIER_INIT(sb + ASM_MBPV, 1);
        MBARRIER_INIT(sb + ASM_MBK0, 512);
        MBARRIER_INIT(sb + ASM_MBK1, 512);
    }
    __syncthreads();   // barriers visible before any cp.async arrives on them

    // Q tile
#pragma unroll
    for (int p = 0; p < 2; p++) {
        int i = tid + p*512; int rr = i >> 3; int c16 = (i & 7) << 4;
        uint32_t so = SMEM_SWIZZLE_128B(rr*128 + c16);
        *(uint4*)(smem + ASM_QH + so) = *(const uint4*)(qh + (size_t)(q0+rr)*128 + c16);
        *(uint4*)(smem + ASM_QL + so) = *(const uint4*)(ql + (size_t)(q0+rr)*128 + c16);
    }
    // K/V(0) -> buf0, arrivals on MBK0
    {
#pragma unroll
        for (int p = 0; p < 2; p++) {
            int i = tid + p*512; int rr = i >> 3; int c16 = (i & 7) << 4;
            uint32_t so = SMEM_SWIZZLE_128B(rr*128 + c16);
            CP_ASYNC16(sb + ASM_K0H + so, kh + (size_t)rr*128 + c16);
            CP_ASYNC16(sb + ASM_K0L + so, kl + (size_t)rr*128 + c16);
        }
#pragma unroll
        for (int p = 0; p < 2; p++) {
            int i = tid + p*512; int d = i >> 4; int j = i & 15;
            uint32_t bo = (uint32_t)((((d>>3) + (j>>3)*8) << 10) + ((d & 7) << 7) + ((j & 7) << 4));
            CP_ASYNC16(sb + ASM_V + SMEM_SWIZZLE_128B(bo), vt + ((size_t)d*TT + j*8)*2);
        }
        CP_MBAR_ARRIVE_NOINC(sb + ASM_MBK0);
        CP_COMMIT();
    }
    // prefetch K/V(1) -> buf1, arrivals on MBK1
    if (qt > 0) {
#pragma unroll
        for (int p = 0; p < 2; p++) {
            int i = tid + p*512; int rr = i >> 3; int c16 = (i & 7) << 4;
            uint32_t so = SMEM_SWIZZLE_128B(rr*128 + c16);
            CP_ASYNC16(sb + ASM_K1H + so, kh + (size_t)(128+rr)*128 + c16);
            CP_ASYNC16(sb + ASM_K1L + so, kl + (size_t)(128+rr)*128 + c16);
        }
#pragma unroll
        for (int p = 0; p < 2; p++) {
            int i = tid + p*512; int d = i >> 4; int j = i & 15;
            uint32_t bo = (uint32_t)((((d>>3) + (j>>3)*8) << 10) + ((d & 7) << 7) + ((j & 7) << 4));
            CP_ASYNC16(sb + ASM_V + 16384 + SMEM_SWIZZLE_128B(bo),
                       vt + ((size_t)d*TT + 128 + j*8)*2);
        }
        CP_MBAR_ARRIVE_NOINC(sb + ASM_MBK1);
        CP_COMMIT();
    }
    __syncthreads();   // tmem ptr visible
    uint32_t tmem;
    asm volatile("ld.shared.b32 %0, [%1];" : "=r"(tmem) : "r"(sb + ASM_TPTR));

    const uint64_t dQh = MAKE_SMEM_DESC(sb+ASM_QH), dQl = MAKE_SMEM_DESC(sb+ASM_QL);
    const uint64_t dP  = MAKE_SMEM_DESC(sb+ASM_P);
    const uint64_t dK[2][2] = {
        { MAKE_SMEM_DESC(sb+ASM_K0H), MAKE_SMEM_DESC(sb+ASM_K0L) },
        { MAKE_SMEM_DESC(sb+ASM_K1H), MAKE_SMEM_DESC(sb+ASM_K1L) } };
    const uint32_t mbS[2] = { sb + ASM_MBS0, sb + ASM_MBS1 };
    const uint32_t mbK[2] = { sb + ASM_MBK0, sb + ASM_MBK1 };

    // S(0): warp 0 waits tile-0 arrivals on MBK0 phase 0
    if (w == 0) {
        MBARRIER_WAIT_PARITY(mbK[0], 0);
        FENCE_PROXY_ASYNC();
        if (elect_one()) {
#pragma unroll
            for (int ks = 0; ks < 4; ks++) {
                mma_f16_ss_cg1(tmem, dQh + ks*2, dK[0][0] + ks*2, IDESC_S, ks > 0);
                mma_f16_ss_cg1(tmem, dQh + ks*2, dK[0][1] + ks*2, IDESC_S, 1u);
                mma_f16_ss_cg1(tmem, dQl + ks*2, dK[0][0] + ks*2, IDESC_S, 1u);
            }
            TCGEN05_COMMIT(mbS[0]);
        }
    }

    float lsum = 0.f;
    const uint32_t pbase = (uint32_t)((((r>>3) + (cq>>1)*16) << 10) + ((r & 7) << 7) + ((cq & 1) << 6));

    for (int kt = 0; kt <= qt; kt++) {
        const int buf = kt & 1;

        // warp 0: once K/V(kt+1) landed, issue S(kt+1) into other TMEM buf
        if (kt < qt && w == 0) {
            const int nb = (kt + 1) & 1;
            MBARRIER_WAIT_PARITY(mbK[nb], ((kt + 1) >> 1) & 1);
            FENCE_PROXY_ASYNC();
            if (elect_one()) {
#pragma unroll
                for (int ks = 0; ks < 4; ks++) {
                    mma_f16_ss_cg1(tmem + nb*128, dQh + ks*2, dK[nb][0] + ks*2, IDESC_S, ks > 0);
                    mma_f16_ss_cg1(tmem + nb*128, dQh + ks*2, dK[nb][1] + ks*2, IDESC_S, 1u);
                    mma_f16_ss_cg1(tmem + nb*128, dQl + ks*2, dK[nb][0] + ks*2, IDESC_S, 1u);
                }
                TCGEN05_COMMIT(mbS[nb]);
            }
        }

        // S(kt) ready (all threads)
        MBARRIER_WAIT_PARITY(mbS[buf], (kt >> 1) & 1);
        TCGEN05_FENCE_AFTER();

        // epilogue: each warp one 32x32 quadrant
        const bool diag = (kt == qt);
        uint32_t sreg[32];
        LDTM_X32(sreg, tmem + buf*128 + cq*32);
        TCGEN05_WAIT_LD();
        uint32_t hp[16];
#pragma unroll
        for (int j2 = 0; j2 < 16; j2++) {
            float e0 = __expf(__uint_as_float(sreg[2*j2])   * ATT_SCALE);
            float e1 = __expf(__uint_as_float(sreg[2*j2+1]) * ATT_SCALE);
            if (diag) {
                int c = cq*32 + 2*j2;
                if (c     > r) e0 = 0.f;
                if (c + 1 > r) e1 = 0.f;
            }
            lsum += e0 + e1;
            __half2 hh = __floats2half2_rn(e0, e1);
            hp[j2] = *(uint32_t*)&hh;
        }

        // PV(kt-1) retired -> P buffer and V slot writable
        if (kt > 0) MBARRIER_WAIT_PARITY(sb + ASM_MBPV, (kt-1) & 1);
#pragma unroll
        for (int k4 = 0; k4 < 4; k4++) {
            uint32_t so = SMEM_SWIZZLE_128B(pbase + k4*16);
            *(uint4*)(smem + ASM_P + so) = ((uint4*)hp)[k4];
        }

        // prefetch K/V(kt+2) into buf kt&1 (S(kt) done per mbS wait above)
        if (kt + 2 <= qt) {
            const int k2 = (kt + 2) * 128;
            const uint32_t nKH = sb + (buf ? ASM_K1H : ASM_K0H);
            const uint32_t nKL = sb + (buf ? ASM_K1L : ASM_K0L);
            const uint32_t nV  = sb + ASM_V + ((kt + 2) % 3) * 16384;
#pragma unroll
            for (int p = 0; p < 2; p++) {
                int i = tid + p*512; int rr = i >> 3; int c16 = (i & 7) << 4;
                uint32_t so = SMEM_SWIZZLE_128B(rr*128 + c16);
                CP_ASYNC16(nKH + so, kh + (size_t)(k2+rr)*128 + c16);
                CP_ASYNC16(nKL + so, kl + (size_t)(k2+rr)*128 + c16);
            }
#pragma unroll
            for (int p = 0; p < 2; p++) {
                int i = tid + p*512; int d = i >> 4; int j = i & 15;
                uint32_t bo = (uint32_t)((((d>>3) + (j>>3)*8) << 10) + ((d & 7) << 7) + ((j & 7) << 4));
                CP_ASYNC16(nV + SMEM_SWIZZLE_128B(bo), vt + ((size_t)d*TT + k2 + j*8)*2);
            }
            CP_MBAR_ARRIVE_NOINC(mbK[buf]);
            CP_COMMIT();
        }

        // P visible to MMA: producers arrive on bar 1; warp 0 syncs then issues PV
        FENCE_PROXY_ASYNC();
        if (w == 0) {
            BAR_SYNC(1, 512);
            TCGEN05_FENCE_BEFORE();
            if (elect_one()) {
                const uint64_t dV = MAKE_SMEM_DESC(sb + ASM_V + (kt % 3) * 16384);
#pragma unroll
                for (int ks = 0; ks < 8; ks++) {
                    uint32_t po = (ks < 4) ? ks*2 : 1024 + (ks-4)*2;
                    uint32_t vo = (ks < 4) ? ks*2 : 512  + (ks-4)*2;
                    uint32_t en0 = (kt > 0 || ks > 0) ? 1u : 0u;
                    mma_f16_ss_cg1(tmem + 256, dP + po, dV + vo, IDESC_PV_F16, en0);
                }
                TCGEN05_COMMIT(sb + ASM_MBPV);
            }
        } else {
            BAR_ARRIVE(1, 512);
        }
    }
    CP_WAIT0();
    MBARRIER_WAIT_PARITY(sb + ASM_MBPV, qt & 1);
    TCGEN05_FENCE_AFTER();

    // O epilogue
    *(float*)(smem + ASM_LP + (cq*128 + r)*4) = lsum;
    __syncthreads();
    if (cq < 2) {
        uint32_t oreg[32];
        LDTM_X32(oreg, tmem + 256 + cq*32);
        TCGEN05_WAIT_LD();
        float lt = *(float*)(smem + ASM_LP + r*4)
                 + *(float*)(smem + ASM_LP + (128 + r)*4)
                 + *(float*)(smem + ASM_LP + (256 + r)*4)
                 + *(float*)(smem + ASM_LP + (384 + r)*4);
        float inv = 1.f / lt;
        const int b2 = bh / HH, h2 = bh % HH;
        size_t oo = ((size_t)(b2*TT + q0 + r)*DD + h2*HDIM + cq*32) * 2;
        uint32_t hp[16], lp[16];
#pragma unroll
        for (int j2 = 0; j2 < 16; j2++) {
            float e0 = __uint_as_float(oreg[2*j2])   * inv;
            float e1 = __uint_as_float(oreg[2*j2+1]) * inv;
            __nv_bfloat16 h0 = __float2bfloat16(e0), h1 = __float2bfloat16(e1);
            __nv_bfloat16 l0 = __float2bfloat16(e0 - __bfloat162float(h0));
            __nv_bfloat16 l1 = __float2bfloat16(e1 - __bfloat162float(h1));
            __nv_bfloat162 hh = __halves2bfloat162(h0, h1);
            __nv_bfloat162 ll = __halves2bfloat162(l0, l1);
            hp[j2] = *(uint32_t*)&hh; lp[j2] = *(uint32_t*)&ll;
        }
#pragma unroll
        for (int k4 = 0; k4 < 4; k4++) {
            *(uint4*)((char*)g_ahi + oo + k4*16) = ((uint4*)hp)[k4];
            *(uint4*)((char*)g_alo + oo + k4*16) = ((uint4*)lp)[k4];
        }
    }
    __syncthreads();
    if (w == 0) TCGEN05_DEALLOC(tmem, 512);
#endif
}

// ---------------------------------------------------------------------------
extern "C" void kernel_launch(void* const* d_in, const int* in_sizes, int n_in,
                              void* d_out, int out_size)
{
    const float* x     = (const float*)d_in[0];
    const float* W_qkv = (const float*)d_in[1];
    const float* b_qkv = (const float*)d_in[2];
    const float* W_out = (const float*)d_in[3];
    const float* b_out = (const float*)d_in[4];
    float* out = (float*)d_out;

    void* p;
    cudaGetSymbolAddress(&p, g_xhi);    __nv_bfloat16* xhi = (__nv_bfloat16*)p;
    cudaGetSymbolAddress(&p, g_xlo);    __nv_bfloat16* xlo = (__nv_bfloat16*)p;
    cudaGetSymbolAddress(&p, g_ahi);    __nv_bfloat16* ahi = (__nv_bfloat16*)p;
    cudaGetSymbolAddress(&p, g_alo);    __nv_bfloat16* alo = (__nv_bfloat16*)p;
    cudaGetSymbolAddress(&p, g_wqt_hi); __nv_bfloat16* wqh = (__nv_bfloat16*)p;
    cudaGetSymbolAddress(&p, g_wqt_lo); __nv_bfloat16* wql = (__nv_bfloat16*)p;
    cudaGetSymbolAddress(&p, g_wot_hi); __nv_bfloat16* woh = (__nv_bfloat16*)p;
    cudaGetSymbolAddress(&p, g_wot_lo); __nv_bfloat16* wol = (__nv_bfloat16*)p;

    const int M = BB * TT;  // 8192

    {
        int n4 = M * DD / 4;
        split_hl<<<(n4 + 255) / 256, 256>>>(x, xhi, xlo, n4);
        tsplit_kernel<<<dim3(DD/32, QKV3/32), dim3(32, 8)>>>(W_qkv, wqh, wql, DD, QKV3);
        tsplit_kernel<<<dim3(DD/32, DD/32),   dim3(32, 8)>>>(W_out, woh, wol, DD, DD);
    }

    cudaFuncSetAttribute(gemm_any, cudaFuncAttributeMaxDynamicSharedMemorySize, GEMM_SMEM);

    // 1) QKV projection with fused split/transpose epilogue (mode 1)
    gemm_any<<<dim3(QKV3/256, M/128), 256, GEMM_SMEM>>>(
        xhi, xlo, wqh, wql, b_qkv, nullptr, M, QKV3, DD, 1);

    // 2) attention -> g_ahi/g_alo
    cudaFuncSetAttribute(attn_tc, cudaFuncAttributeMaxDynamicSharedMemorySize, ATT_SMEM);
    attn_tc<<<dim3(TT/128, BB*HH), 512, ATT_SMEM>>>();

    // 3) output projection (mode 0)
    gemm_any<<<dim3(DD/256, M/128), 256, GEMM_SMEM>>>(
        ahi, alo, woh, wol, b_out, out, M, DD, DD, 0);
}